// round 2
// baseline (speedup 1.0000x reference)
#include <cuda_runtime.h>

// FraudDetectionHybrid — fused, dead-code-eliminated.
// Output depends only on: fraud net (4x tanh 2x2), conv-sigmoid, sampler QNN, softmax.
// The whole autoencoder (enc_*/dec_*) is dead code in the reference and is skipped.

#define LOG2E_F 1.4426950408889634f

static __device__ __forceinline__ float ex2_fast(float x) {
    float y;
    asm("ex2.approx.f32 %0, %1;" : "=f"(y) : "f"(x));
    return y;
}
static __device__ __forceinline__ float rcp_fast(float x) {
    float y;
    asm("rcp.approx.f32 %0, %1;" : "=f"(y) : "f"(x));
    return y;
}

// tanh(a) where A = 2*log2(e)*a has been pre-scaled into the weights:
// tanh(a) = 1 - 2 / (exp(2a) + 1) = 1 - 2 / (ex2(A) + 1)
static __device__ __forceinline__ float tanh_pre(float A) {
    return fmaf(-2.0f, rcp_fast(ex2_fast(A) + 1.0f), 1.0f);
}

constexpr int B_TOTAL  = 1048576;
constexpr int THREADS  = 256;
constexpr int BLOCKS   = 1024;
constexpr int NTHREADS = THREADS * BLOCKS;   // 262144
constexpr int ITERS    = B_TOTAL / NTHREADS; // 4

__global__ __launch_bounds__(THREADS)
void fraud_fused_kernel(const float2* __restrict__ x,
                        const float*  __restrict__ fW,   // [4,2,2]
                        const float*  __restrict__ fb,   // [4,2]
                        const float*  __restrict__ ck,   // [2,2]
                        const float*  __restrict__ w1,   // [4,2]
                        const float*  __restrict__ b1,   // [4]
                        const float*  __restrict__ w2,   // [2,4]
                        const float*  __restrict__ b2,   // [2]
                        float2*       __restrict__ out)
{
    const float S = 2.0f * LOG2E_F;

    // ---- load + pre-scale weights into registers (uniform, L1-broadcast) ----
    float FW00[4], FW01[4], FW10[4], FW11[4], FB0[4], FB1[4];
#pragma unroll
    for (int l = 0; l < 4; ++l) {
        FW00[l] = S * __ldg(&fW[l * 4 + 0]);
        FW01[l] = S * __ldg(&fW[l * 4 + 1]);
        FW10[l] = S * __ldg(&fW[l * 4 + 2]);
        FW11[l] = S * __ldg(&fW[l * 4 + 3]);
        FB0[l]  = S * __ldg(&fb[l * 2 + 0]);
        FB1[l]  = S * __ldg(&fb[l * 2 + 1]);
    }

    // conv: patch = [[h0,h1],[h0,h1]] -> sum = h0*(k00+k10) + h1*(k01+k11)
    // sigmoid(d) = rcp(1 + ex2(-log2e * d)); fold -log2e into coefficients
    const float C0 = -LOG2E_F * (__ldg(&ck[0]) + __ldg(&ck[2]));
    const float C1 = -LOG2E_F * (__ldg(&ck[1]) + __ldg(&ck[3]));

    float W1a[4], W1b[4], B1v[4];
#pragma unroll
    for (int j = 0; j < 4; ++j) {
        W1a[j] = S * __ldg(&w1[j * 2 + 0]);
        W1b[j] = S * __ldg(&w1[j * 2 + 1]);
        B1v[j] = S * __ldg(&b1[j]);
    }

    // 2-way softmax: p0 = sigmoid(l0 - l1); fold -log2e into the diff weights
    float WD[4];
#pragma unroll
    for (int j = 0; j < 4; ++j)
        WD[j] = -LOG2E_F * (__ldg(&w2[j]) - __ldg(&w2[4 + j]));
    const float BD = -LOG2E_F * (__ldg(&b2[0]) - __ldg(&b2[1]));

    const int tid = blockIdx.x * blockDim.x + threadIdx.x;

#pragma unroll
    for (int it = 0; it < ITERS; ++it) {
        const int i = tid + it * NTHREADS;
        const float2 v = __ldg(&x[i]);
        float h0 = v.x, h1 = v.y;

        // fraud net: 4 layers of tanh(W h + b), weights pre-scaled by 2*log2e
#pragma unroll
        for (int l = 0; l < 4; ++l) {
            const float a0 = fmaf(FW00[l], h0, fmaf(FW01[l], h1, FB0[l]));
            const float a1 = fmaf(FW10[l], h0, fmaf(FW11[l], h1, FB1[l]));
            h0 = tanh_pre(a0);
            h1 = tanh_pre(a1);
        }

        // conv -> sigmoid (scales already folded, arg already negated)
        const float conv = rcp_fast(1.0f + ex2_fast(fmaf(C0, h0, C1 * h1)));

        // sampler hidden layer: 4 tanh neurons on [h0, conv]
        float t0 = tanh_pre(fmaf(W1a[0], h0, fmaf(W1b[0], conv, B1v[0])));
        float t1 = tanh_pre(fmaf(W1a[1], h0, fmaf(W1b[1], conv, B1v[1])));
        float t2 = tanh_pre(fmaf(W1a[2], h0, fmaf(W1b[2], conv, B1v[2])));
        float t3 = tanh_pre(fmaf(W1a[3], h0, fmaf(W1b[3], conv, B1v[3])));

        // softmax over 2 logits == sigmoid of logit diff
        float d = fmaf(WD[0], t0, BD);
        d = fmaf(WD[1], t1, d);
        d = fmaf(WD[2], t2, d);
        d = fmaf(WD[3], t3, d);
        const float p0 = rcp_fast(1.0f + ex2_fast(d));

        out[i] = make_float2(p0, 1.0f - p0);
    }
}

extern "C" void kernel_launch(void* const* d_in, const int* in_sizes, int n_in,
                              void* d_out, int out_size)
{
    // metadata order:
    // 0:x 1:fraud_W 2:fraud_b 3..14:enc/dec (dead) 15:conv_k 16:s_W1 17:s_b1 18:s_W2 19:s_b2
    const float2* x  = (const float2*)d_in[0];
    const float*  fW = (const float*)d_in[1];
    const float*  fb = (const float*)d_in[2];
    const float*  ck = (const float*)d_in[15];
    const float*  w1 = (const float*)d_in[16];
    const float*  b1 = (const float*)d_in[17];
    const float*  w2 = (const float*)d_in[18];
    const float*  b2 = (const float*)d_in[19];
    float2* out = (float2*)d_out;

    (void)in_sizes; (void)n_in; (void)out_size;

    fraud_fused_kernel<<<BLOCKS, THREADS>>>(x, fW, fb, ck, w1, b1, w2, b2, out);
}

// round 3
// speedup vs baseline: 1.4281x; 1.4281x over previous
#include <cuda_runtime.h>

// FraudDetectionHybrid — fused, dead-code-eliminated, MUFU.TANH everywhere.
// Output depends only on: fraud net (4x tanh 2x2), conv-sigmoid, sampler QNN, softmax.
// Autoencoder (enc_*/dec_*) is dead code and skipped.
// All sigmoids rewritten as 0.5 + 0.5*tanh(y/2) with the 0.5 scale/shift folded
// into downstream weights at register-setup time (zero per-sample cost).

static __device__ __forceinline__ float tanh_fast(float x) {
    float y;
    asm("tanh.approx.f32 %0, %1;" : "=f"(y) : "f"(x));
    return y;
}

constexpr int B_TOTAL  = 1048576;
constexpr int THREADS  = 256;
constexpr int BLOCKS   = 1024;
constexpr int NTHREADS = THREADS * BLOCKS;    // 262144
constexpr int ITERS    = B_TOTAL / NTHREADS;  // 4 samples/thread -> 2 float4 iters

struct Coefs {
    float FW00[4], FW01[4], FW10[4], FW11[4], FB0[4], FB1[4];
    float C0, C1;
    float W1a[4], W1bh[4], B1v[4];
    float WD[4], BD;
};

__global__ __launch_bounds__(THREADS)
void fraud_fused_kernel(const float4* __restrict__ x,
                        const float*  __restrict__ fW,   // [4,2,2]
                        const float*  __restrict__ fb,   // [4,2]
                        const float*  __restrict__ ck,   // [2,2]
                        const float*  __restrict__ w1,   // [4,2]
                        const float*  __restrict__ b1,   // [4]
                        const float*  __restrict__ w2,   // [2,4]
                        const float*  __restrict__ b2,   // [2]
                        float4*       __restrict__ out)
{
    Coefs c;
#pragma unroll
    for (int l = 0; l < 4; ++l) {
        c.FW00[l] = __ldg(&fW[l * 4 + 0]);
        c.FW01[l] = __ldg(&fW[l * 4 + 1]);
        c.FW10[l] = __ldg(&fW[l * 4 + 2]);
        c.FW11[l] = __ldg(&fW[l * 4 + 3]);
        c.FB0[l]  = __ldg(&fb[l * 2 + 0]);
        c.FB1[l]  = __ldg(&fb[l * 2 + 1]);
    }

    // conv: patch rows identical -> s = (k00+k10)*h0 + (k01+k11)*h1
    // sigmoid(s) = 0.5 + 0.5*tanh(s/2): fold the /2 into the coefficients,
    // and fold the 0.5/0.5 affine into the sampler weights below.
    c.C0 = 0.5f * (__ldg(&ck[0]) + __ldg(&ck[2]));
    c.C1 = 0.5f * (__ldg(&ck[1]) + __ldg(&ck[3]));

#pragma unroll
    for (int j = 0; j < 4; ++j) {
        const float wa = __ldg(&w1[j * 2 + 0]);
        const float wb = __ldg(&w1[j * 2 + 1]);
        c.W1a[j]  = wa;
        c.W1bh[j] = 0.5f * wb;                   // multiplies tanh(conv_arg)
        c.B1v[j]  = __ldg(&b1[j]) + 0.5f * wb;   // absorbs the +0.5 shift
    }

    // softmax over 2 logits: p0 = sigmoid(l0-l1) = 0.5 + 0.5*tanh((l0-l1)/2)
#pragma unroll
    for (int j = 0; j < 4; ++j)
        c.WD[j] = 0.5f * (__ldg(&w2[j]) - __ldg(&w2[4 + j]));
    c.BD = 0.5f * (__ldg(&b2[0]) - __ldg(&b2[1]));

    const int tid = blockIdx.x * blockDim.x + threadIdx.x;

#pragma unroll
    for (int it = 0; it < ITERS / 2; ++it) {
        const int i = tid + it * NTHREADS;       // float4 index = 2 samples
        const float4 v = __ldg(&x[i]);

        float h0[2] = {v.x, v.z};
        float h1[2] = {v.y, v.w};
        float p0[2];

#pragma unroll
        for (int s = 0; s < 2; ++s) {
            float a0 = h0[s], a1 = h1[s];
            // fraud net: 4 layers tanh(W h + b)
#pragma unroll
            for (int l = 0; l < 4; ++l) {
                const float t0 = fmaf(c.FW00[l], a0, fmaf(c.FW01[l], a1, c.FB0[l]));
                const float t1 = fmaf(c.FW10[l], a0, fmaf(c.FW11[l], a1, c.FB1[l]));
                a0 = tanh_fast(t0);
                a1 = tanh_fast(t1);
            }

            // conv sigmoid half-arg -> tanh; 0.5/0.5 folded into sampler coefs
            const float tc = tanh_fast(fmaf(c.C0, a0, c.C1 * a1));

            // sampler hidden: 4 tanh neurons on [a0, sigmoid(conv)]
            const float q0 = tanh_fast(fmaf(c.W1a[0], a0, fmaf(c.W1bh[0], tc, c.B1v[0])));
            const float q1 = tanh_fast(fmaf(c.W1a[1], a0, fmaf(c.W1bh[1], tc, c.B1v[1])));
            const float q2 = tanh_fast(fmaf(c.W1a[2], a0, fmaf(c.W1bh[2], tc, c.B1v[2])));
            const float q3 = tanh_fast(fmaf(c.W1a[3], a0, fmaf(c.W1bh[3], tc, c.B1v[3])));

            // half logit-diff, then p0 = 0.5 + 0.5*tanh(d)
            float d = fmaf(c.WD[0], q0, c.BD);
            d = fmaf(c.WD[1], q1, d);
            d = fmaf(c.WD[2], q2, d);
            d = fmaf(c.WD[3], q3, d);
            p0[s] = fmaf(0.5f, tanh_fast(d), 0.5f);
        }

        out[i] = make_float4(p0[0], 1.0f - p0[0], p0[1], 1.0f - p0[1]);
    }
}

extern "C" void kernel_launch(void* const* d_in, const int* in_sizes, int n_in,
                              void* d_out, int out_size)
{
    // metadata order:
    // 0:x 1:fraud_W 2:fraud_b 3..14:enc/dec (dead) 15:conv_k 16:s_W1 17:s_b1 18:s_W2 19:s_b2
    const float4* x  = (const float4*)d_in[0];
    const float*  fW = (const float*)d_in[1];
    const float*  fb = (const float*)d_in[2];
    const float*  ck = (const float*)d_in[15];
    const float*  w1 = (const float*)d_in[16];
    const float*  b1 = (const float*)d_in[17];
    const float*  w2 = (const float*)d_in[18];
    const float*  b2 = (const float*)d_in[19];
    float4* out = (float4*)d_out;

    (void)in_sizes; (void)n_in; (void)out_size;

    fraud_fused_kernel<<<BLOCKS, THREADS>>>(x, fW, fb, ck, w1, b1, w2, b2, out);
}

// round 4
// speedup vs baseline: 1.4640x; 1.0252x over previous
#include <cuda_runtime.h>

// FraudDetectionHybrid — fused, dead-code-eliminated, MUFU.TANH, ILP=4.
// Latency-bound fix: all 4 samples per thread advance through the tanh-chain
// concurrently (interleaved), quadrupling independent MUFU streams per warp.

static __device__ __forceinline__ float tanh_fast(float x) {
    float y;
    asm("tanh.approx.f32 %0, %1;" : "=f"(y) : "f"(x));
    return y;
}

constexpr int B_TOTAL  = 1048576;
constexpr int THREADS  = 256;
constexpr int BLOCKS   = 1024;
constexpr int NTHREADS = THREADS * BLOCKS;    // 262144 threads, 4 samples each

__global__ __launch_bounds__(THREADS)
void fraud_fused_kernel(const float4* __restrict__ x,
                        const float*  __restrict__ fW,   // [4,2,2]
                        const float*  __restrict__ fb,   // [4,2]
                        const float*  __restrict__ ck,   // [2,2]
                        const float*  __restrict__ w1,   // [4,2]
                        const float*  __restrict__ b1,   // [4]
                        const float*  __restrict__ w2,   // [2,4]
                        const float*  __restrict__ b2,   // [2]
                        float4*       __restrict__ out)
{
    // ---- coefficient setup (uniform per thread, L1-broadcast loads) ----
    float FW00[4], FW01[4], FW10[4], FW11[4], FB0[4], FB1[4];
#pragma unroll
    for (int l = 0; l < 4; ++l) {
        FW00[l] = __ldg(&fW[l * 4 + 0]);
        FW01[l] = __ldg(&fW[l * 4 + 1]);
        FW10[l] = __ldg(&fW[l * 4 + 2]);
        FW11[l] = __ldg(&fW[l * 4 + 3]);
        FB0[l]  = __ldg(&fb[l * 2 + 0]);
        FB1[l]  = __ldg(&fb[l * 2 + 1]);
    }

    // conv rows identical: s = (k00+k10)*h0 + (k01+k11)*h1
    // sigmoid(s) = 0.5 + 0.5*tanh(s/2); halves folded here, affine folded below.
    const float C0 = 0.5f * (__ldg(&ck[0]) + __ldg(&ck[2]));
    const float C1 = 0.5f * (__ldg(&ck[1]) + __ldg(&ck[3]));

    float W1a[4], W1bh[4], B1v[4];
#pragma unroll
    for (int j = 0; j < 4; ++j) {
        const float wa = __ldg(&w1[j * 2 + 0]);
        const float wb = __ldg(&w1[j * 2 + 1]);
        W1a[j]  = wa;
        W1bh[j] = 0.5f * wb;
        B1v[j]  = __ldg(&b1[j]) + 0.5f * wb;
    }

    // softmax(2) == sigmoid(l0-l1) = 0.5 + 0.5*tanh((l0-l1)/2)
    float WD[4];
#pragma unroll
    for (int j = 0; j < 4; ++j)
        WD[j] = 0.5f * (__ldg(&w2[j]) - __ldg(&w2[4 + j]));
    const float BD = 0.5f * (__ldg(&b2[0]) - __ldg(&b2[1]));

    const int tid = blockIdx.x * blockDim.x + threadIdx.x;

    // ---- load 4 samples (two float4s), run all 4 chains interleaved ----
    const float4 va = __ldg(&x[tid]);
    const float4 vb = __ldg(&x[tid + NTHREADS]);

    float a0[4], a1[4];
    a0[0] = va.x; a1[0] = va.y;
    a0[1] = va.z; a1[1] = va.w;
    a0[2] = vb.x; a1[2] = vb.y;
    a0[3] = vb.z; a1[3] = vb.w;

    // fraud net: 4 layers of tanh(W h + b), 4 samples in lockstep
#pragma unroll
    for (int l = 0; l < 4; ++l) {
        float t0[4], t1[4];
#pragma unroll
        for (int s = 0; s < 4; ++s) {
            t0[s] = fmaf(FW00[l], a0[s], fmaf(FW01[l], a1[s], FB0[l]));
            t1[s] = fmaf(FW10[l], a0[s], fmaf(FW11[l], a1[s], FB1[l]));
        }
#pragma unroll
        for (int s = 0; s < 4; ++s) {
            a0[s] = tanh_fast(t0[s]);
            a1[s] = tanh_fast(t1[s]);
        }
    }

    // conv sigmoid (as tanh of half-arg), interleaved
    float tc[4];
#pragma unroll
    for (int s = 0; s < 4; ++s)
        tc[s] = tanh_fast(fmaf(C0, a0[s], C1 * a1[s]));

    // sampler hidden: 4 tanh neurons per sample; 16 independent MUFUs
    float q[4][4];
#pragma unroll
    for (int s = 0; s < 4; ++s) {
#pragma unroll
        for (int j = 0; j < 4; ++j)
            q[s][j] = tanh_fast(fmaf(W1a[j], a0[s], fmaf(W1bh[j], tc[s], B1v[j])));
    }

    // half logit-diff -> p0 = 0.5 + 0.5*tanh(d)
    float p0[4];
#pragma unroll
    for (int s = 0; s < 4; ++s) {
        float d = fmaf(WD[0], q[s][0], BD);
        d = fmaf(WD[1], q[s][1], d);
        d = fmaf(WD[2], q[s][2], d);
        d = fmaf(WD[3], q[s][3], d);
        p0[s] = fmaf(0.5f, tanh_fast(d), 0.5f);
    }

    out[tid]            = make_float4(p0[0], 1.0f - p0[0], p0[1], 1.0f - p0[1]);
    out[tid + NTHREADS] = make_float4(p0[2], 1.0f - p0[2], p0[3], 1.0f - p0[3]);
}

extern "C" void kernel_launch(void* const* d_in, const int* in_sizes, int n_in,
                              void* d_out, int out_size)
{
    // metadata order:
    // 0:x 1:fraud_W 2:fraud_b 3..14:enc/dec (dead) 15:conv_k 16:s_W1 17:s_b1 18:s_W2 19:s_b2
    const float4* x  = (const float4*)d_in[0];
    const float*  fW = (const float*)d_in[1];
    const float*  fb = (const float*)d_in[2];
    const float*  ck = (const float*)d_in[15];
    const float*  w1 = (const float*)d_in[16];
    const float*  b1 = (const float*)d_in[17];
    const float*  w2 = (const float*)d_in[18];
    const float*  b2 = (const float*)d_in[19];
    float4* out = (float4*)d_out;

    (void)in_sizes; (void)n_in; (void)out_size;

    fraud_fused_kernel<<<BLOCKS, THREADS>>>(x, fW, fb, ck, w1, b1, w2, b2, out);
}